// round 14
// baseline (speedup 1.0000x reference)
#include <cuda_runtime.h>

#define NEG_SLOPE 0.2f

// Node-sized scratch (N = 100000, capacity 131072)
static __device__ float2 g_spack[131072];   // {a_src, h}          indexed by src
static __device__ float4 g_dnode[131072];   // {a_dst, eself, numer, denom} indexed by dst
                                            // d-gather (.x) and vec-atomic (.z/.w) share a sector
// Edge-sized scratch: per-edge exp value p[j]
static __device__ float  g_p[3300000];

__device__ __forceinline__ float lrelu(float e) {
    return e > 0.0f ? e : NEG_SLOPE * e;
}

__device__ __forceinline__ void red_add_v2(float* addr8, float x, float y) {
    asm volatile("red.global.add.v2.f32 [%0], {%1, %2};"
                 :: "l"(addr8), "f"(x), "f"(y) : "memory");
}

// Per-block dtype probe: int64 little-endian with values < 2^31 => sampled odd
// int32 slots are all zero. 64 L2-hit loads per block; no separate kernel.
__device__ __forceinline__ int probe_is64(const int* __restrict__ ei32, int E) {
    __shared__ int s_nz;
    if (threadIdx.x == 0) s_nz = 0;
    __syncthreads();
    if (threadIdx.x < 64) {
        int stride = (2 * E) / 64;
        if (ei32[1 + (size_t)threadIdx.x * stride] != 0) atomicAdd(&s_nz, 1);
    }
    __syncthreads();
    return s_nz == 0;
}

__device__ __forceinline__ void load_edges4(const void* __restrict__ ei, int E, int N,
                                            int base, int is64, int* s, int* d) {
    if (!is64) {
        const int* e32 = (const int*)ei;
        int4 sv = *reinterpret_cast<const int4*>(e32 + base);
        int4 dv = *reinterpret_cast<const int4*>(e32 + (size_t)E + base);
        s[0] = sv.x; s[1] = sv.y; s[2] = sv.z; s[3] = sv.w;
        d[0] = dv.x; d[1] = dv.y; d[2] = dv.z; d[3] = dv.w;
    } else {
        const long long* e64 = (const long long*)ei;
#pragma unroll
        for (int k = 0; k < 4; k++) {
            s[k] = (int)e64[base + k];
            d[k] = (int)e64[(size_t)E + base + k];
        }
    }
#pragma unroll
    for (int k = 0; k < 4; k++) {
        if ((unsigned)s[k] >= (unsigned)N) s[k] = 0;
        if ((unsigned)d[k] >= (unsigned)N) d[k] = 0;
    }
}

__device__ __forceinline__ void load_edge1(const void* __restrict__ ei, int E, int N,
                                           int j, int is64, int& s, int& d) {
    if (!is64) {
        const int* e32 = (const int*)ei;
        s = e32[j];
        d = e32[(size_t)E + j];
    } else {
        const long long* e64 = (const long long*)ei;
        s = (int)e64[j];
        d = (int)e64[(size_t)E + j];
    }
    if ((unsigned)s >= (unsigned)N) s = 0;
    if ((unsigned)d >= (unsigned)N) d = 0;
}

// KA (fused): blocks [0, ebA) copy edge indices to float output streams;
// blocks [ebA, ...) do the node pass with 4 nodes per warp (MLP=4).
__global__ void k_fuseA(const void* __restrict__ ei, const float* __restrict__ x,
                        const float* __restrict__ W,
                        const float* __restrict__ att_src, const float* __restrict__ att_dst,
                        float* __restrict__ out, int E, int N, long long M, int ebA) {
    int tid = threadIdx.x;
    if ((int)blockIdx.x < ebA) {
        // ---- index-copy role ----
        int is64 = probe_is64((const int*)ei, E);
        int base = (blockIdx.x * blockDim.x + tid) * 4;
        if (base >= E) return;
        if (base + 4 <= E) {
            int s[4], d[4];
            load_edges4(ei, E, N, base, is64, s, d);
            size_t b = (size_t)N + base;
            float4 fs = make_float4((float)s[0], (float)s[1], (float)s[2], (float)s[3]);
            float4 fd = make_float4((float)d[0], (float)d[1], (float)d[2], (float)d[3]);
            __stcs(reinterpret_cast<float4*>(out + b), fs);
            __stcs(reinterpret_cast<float4*>(out + b + M), fd);
        } else {
            for (int j = base; j < E; j++) {
                int s, d;
                load_edge1(ei, E, N, j, is64, s, d);
                out[(size_t)N + j]     = (float)s;
                out[(size_t)N + M + j] = (float)d;
            }
        }
    } else {
        // ---- node role: 4 nodes per warp, 4 independent loads per lane ----
        __shared__ float sW[128];
        if (tid < 128) sW[tid] = W[tid];
        __syncthreads();

        int gwarp = (((int)blockIdx.x - ebA) * blockDim.x + tid) >> 5;
        int lane  = tid & 31;
        int n0 = gwarp * 4;
        if (n0 >= N) return;

        float4 w = reinterpret_cast<const float4*>(sW)[lane];
        float4 v[4];
#pragma unroll
        for (int r = 0; r < 4; r++) {
            int row = n0 + r;
            if (row >= N) row = 0;                  // safe dummy; store skipped below
            v[r] = __ldcs(reinterpret_cast<const float4*>(x + (size_t)row * 128) + lane);
        }
        float acc[4];
#pragma unroll
        for (int r = 0; r < 4; r++)
            acc[r] = v[r].x * w.x + v[r].y * w.y + v[r].z * w.z + v[r].w * w.w;
#pragma unroll
        for (int o = 16; o; o >>= 1) {
#pragma unroll
            for (int r = 0; r < 4; r++)
                acc[r] += __shfl_xor_sync(0xFFFFFFFFu, acc[r], o);
        }
        if (lane < 4) {
            int node = n0 + lane;
            if (node < N) {
                float h  = acc[lane];
                float as = h * att_src[0];
                float ad = h * att_dst[0];
                float p  = expf(lrelu(as + ad));    // self-loop term
                g_spack[node] = make_float2(as, h);
                g_dnode[node] = make_float4(ad, p, h * p, p); // {ad, eself, numer, denom}
            }
        }
    }
}

// K2: 4 edges/thread. d-side gather (.x) and vec-atomic (.z/.w) hit the SAME
// float4 => 2 random sectors per edge instead of 3.
__global__ void k_edge1(const void* __restrict__ ei, int E, int N) {
    int is64 = probe_is64((const int*)ei, E);
    const float* dbase = &g_dnode[0].x;
    int base = (blockIdx.x * blockDim.x + threadIdx.x) * 4;
    if (base >= E) return;
    if (base + 4 <= E) {
        int s[4], d[4];
        load_edges4(ei, E, N, base, is64, s, d);
        float2 sp[4];
        float  ad[4];
#pragma unroll
        for (int k = 0; k < 4; k++) sp[k] = __ldg(&g_spack[s[k]]);
#pragma unroll
        for (int k = 0; k < 4; k++) ad[k] = __ldg(dbase + 4 * (size_t)d[k]);
        float p[4];
#pragma unroll
        for (int k = 0; k < 4; k++) p[k] = expf(lrelu(sp[k].x + ad[k]));
        *reinterpret_cast<float4*>(g_p + base) = make_float4(p[0], p[1], p[2], p[3]);
#pragma unroll
        for (int k = 0; k < 4; k++)
            red_add_v2(&g_dnode[d[k]].z, sp[k].y * p[k], p[k]);
    } else {
        for (int j = base; j < E; j++) {
            int s, d;
            load_edge1(ei, E, N, j, is64, s, d);
            float2 sp = g_spack[s];
            float p = expf(lrelu(sp.x + g_dnode[d].x));
            g_p[j] = p;
            red_add_v2(&g_dnode[d].z, sp.y * p, p);
        }
    }
}

// KB (fused): blocks [0, nb2) finalize scores + self-loop slots; blocks
// [nb2, ...) produce per-edge alpha (gather denom = g_dnode[d].w).
__global__ void k_fuseB(float* __restrict__ out, const float* __restrict__ bias,
                        int E, int N, long long Ell, long long M, int full, int nb2) {
    int tid = threadIdx.x;
    if ((int)blockIdx.x < nb2) {
        int i = blockIdx.x * blockDim.x + tid;
        if (i >= N) return;
        float4 nd = g_dnode[i];                   // {ad, eself, numer, denom}
        float inv = 1.0f / (nd.w + 1e-16f);
        out[i] = bias[0] + nd.z * inv;
        if (full) {
            size_t base = (size_t)N;
            float fi = (float)i;
            out[base + Ell + i]         = fi;            // src, self-loop slot
            out[base + M + Ell + i]     = fi;            // dst, self-loop slot
            out[base + 2 * M + Ell + i] = nd.y * inv;    // alpha, self-loop slot
        }
    } else {
        // edge-alpha role: read dst back from out's float-dst stream (exact < 2^24)
        const float* dbase = &g_dnode[0].x;
        int base = (((int)blockIdx.x - nb2) * blockDim.x + tid) * 4;
        if (base >= E) return;
        size_t b = (size_t)N + base;
        if (base + 4 <= E) {
            float4 fd = *reinterpret_cast<const float4*>(out + b + M);
            float4 pv = *reinterpret_cast<const float4*>(g_p + base);
            int d0 = __float2int_rz(fd.x), d1 = __float2int_rz(fd.y);
            int d2 = __float2int_rz(fd.z), d3 = __float2int_rz(fd.w);
            float4 fa = make_float4(pv.x / (__ldg(dbase + 4 * (size_t)d0 + 3) + 1e-16f),
                                    pv.y / (__ldg(dbase + 4 * (size_t)d1 + 3) + 1e-16f),
                                    pv.z / (__ldg(dbase + 4 * (size_t)d2 + 3) + 1e-16f),
                                    pv.w / (__ldg(dbase + 4 * (size_t)d3 + 3) + 1e-16f));
            __stcs(reinterpret_cast<float4*>(out + b + 2 * M), fa);
        } else {
            for (int j = base; j < E; j++) {
                int d = __float2int_rz(out[(size_t)N + M + j]);
                out[(size_t)N + 2 * M + j] = g_p[j] / (g_dnode[d].w + 1e-16f);
            }
        }
    }
}

extern "C" void kernel_launch(void* const* d_in, const int* in_sizes, int n_in,
                              void* d_out, int out_size) {
    const float* x       = (const float*)d_in[0];
    const void*  ei      = d_in[1];
    const float* W       = (const float*)d_in[2];
    const float* att_src = (const float*)d_in[3];
    const float* att_dst = (const float*)d_in[4];
    const float* bias    = (const float*)d_in[5];

    int N = in_sizes[0] / 128;
    int E = in_sizes[1] / 2;
    long long M = (long long)E + N;
    int full = ((long long)out_size >= (long long)N + 3 * M) ? 1 : 0;
    float* out = (float*)d_out;

    int eblocks4 = ((E + 3) / 4 + 255) / 256;     // 4 edges/thread kernels
    int nblocks1 = (N + 31) / 32;                 // node role: 8 warps/block, 4 nodes/warp
    int nblocks2 = (N + 255) / 256;               // node finalize: 1 node/thread

    int ebA = full ? eblocks4 : 0;
    k_fuseA<<<ebA + nblocks1, 256>>>(ei, x, W, att_src, att_dst, out, E, N, M, ebA);
    k_edge1<<<eblocks4, 256>>>(ei, E, N);
    int ebB = full ? eblocks4 : 0;
    k_fuseB<<<nblocks2 + ebB, 256>>>(out, bias, E, N, (long long)E, M, full, nblocks2);
}

// round 15
// speedup vs baseline: 1.1522x; 1.1522x over previous
#include <cuda_runtime.h>

#define NEG_SLOPE 0.2f

// Node-sized scratch (N = 100000, capacity 131072)
static __device__ float  g_a[131072];       // case A: a_src | case B: a_dst | case C: h  (4B/node!)
static __device__ float2 g_acc[131072];     // {numer, denom} accumulated by edge pass
static __device__ float  g_eself[131072];   // self-loop exp term
// Edge-sized scratch: per-edge exp value p[j]
static __device__ float  g_p[3300000];

__device__ __forceinline__ float lrelu(float e) {
    return e > 0.0f ? e : NEG_SLOPE * e;
}

__device__ __forceinline__ void red_add_v2(float2* addr, float x, float y) {
    asm volatile("red.global.add.v2.f32 [%0], {%1, %2};"
                 :: "l"(addr), "f"(x), "f"(y) : "memory");
}

// Uniform case coefficients from the scalar attention weights.
//   p = exp(lrelu(g_a[s]*e_s + g_a[d]*e_d));  h[s] = g_a[s]*h_c
__device__ __forceinline__ void att_coeffs(float a_s, float a_d,
                                           float& e_s, float& e_d, float& h_c) {
    if (a_s != 0.0f)      { e_s = 1.0f; e_d = a_d / a_s; h_c = 1.0f / a_s; }
    else if (a_d != 0.0f) { e_s = 0.0f; e_d = 1.0f;      h_c = 1.0f / a_d; }
    else                  { e_s = 0.0f; e_d = 0.0f;      h_c = 1.0f; }
}

// Per-block dtype probe: int64 little-endian with values < 2^31 => sampled odd
// int32 slots are all zero. 64 L2-hit loads per block; no separate kernel.
__device__ __forceinline__ int probe_is64(const int* __restrict__ ei32, int E) {
    __shared__ int s_nz;
    if (threadIdx.x == 0) s_nz = 0;
    __syncthreads();
    if (threadIdx.x < 64) {
        int stride = (2 * E) / 64;
        if (ei32[1 + (size_t)threadIdx.x * stride] != 0) atomicAdd(&s_nz, 1);
    }
    __syncthreads();
    return s_nz == 0;
}

__device__ __forceinline__ void load_edges4(const void* __restrict__ ei, int E, int N,
                                            int base, int is64, int* s, int* d) {
    if (!is64) {
        const int* e32 = (const int*)ei;
        int4 sv = *reinterpret_cast<const int4*>(e32 + base);
        int4 dv = *reinterpret_cast<const int4*>(e32 + (size_t)E + base);
        s[0] = sv.x; s[1] = sv.y; s[2] = sv.z; s[3] = sv.w;
        d[0] = dv.x; d[1] = dv.y; d[2] = dv.z; d[3] = dv.w;
    } else {
        const long long* e64 = (const long long*)ei;
#pragma unroll
        for (int k = 0; k < 4; k++) {
            s[k] = (int)e64[base + k];
            d[k] = (int)e64[(size_t)E + base + k];
        }
    }
#pragma unroll
    for (int k = 0; k < 4; k++) {
        if ((unsigned)s[k] >= (unsigned)N) s[k] = 0;
        if ((unsigned)d[k] >= (unsigned)N) d[k] = 0;
    }
}

__device__ __forceinline__ void load_edge1(const void* __restrict__ ei, int E, int N,
                                           int j, int is64, int& s, int& d) {
    if (!is64) {
        const int* e32 = (const int*)ei;
        s = e32[j];
        d = e32[(size_t)E + j];
    } else {
        const long long* e64 = (const long long*)ei;
        s = (int)e64[j];
        d = (int)e64[(size_t)E + j];
    }
    if ((unsigned)s >= (unsigned)N) s = 0;
    if ((unsigned)d >= (unsigned)N) d = 0;
}

// KA (fused): blocks [0, ebA) copy edge indices to float output streams;
// blocks [ebA, ...) do the node pass with 4 nodes per warp (MLP=4).
__global__ void k_fuseA(const void* __restrict__ ei, const float* __restrict__ x,
                        const float* __restrict__ W,
                        const float* __restrict__ att_src, const float* __restrict__ att_dst,
                        float* __restrict__ out, int E, int N, long long M, int ebA) {
    int tid = threadIdx.x;
    if ((int)blockIdx.x < ebA) {
        // ---- index-copy role ----
        int is64 = probe_is64((const int*)ei, E);
        int base = (blockIdx.x * blockDim.x + tid) * 4;
        if (base >= E) return;
        if (base + 4 <= E) {
            int s[4], d[4];
            load_edges4(ei, E, N, base, is64, s, d);
            size_t b = (size_t)N + base;
            float4 fs = make_float4((float)s[0], (float)s[1], (float)s[2], (float)s[3]);
            float4 fd = make_float4((float)d[0], (float)d[1], (float)d[2], (float)d[3]);
            __stcs(reinterpret_cast<float4*>(out + b), fs);
            __stcs(reinterpret_cast<float4*>(out + b + M), fd);
        } else {
            for (int j = base; j < E; j++) {
                int s, d;
                load_edge1(ei, E, N, j, is64, s, d);
                out[(size_t)N + j]     = (float)s;
                out[(size_t)N + M + j] = (float)d;
            }
        }
    } else {
        // ---- node role: 4 nodes per warp, 4 independent loads per lane ----
        __shared__ float sW[128];
        if (tid < 128) sW[tid] = W[tid];
        __syncthreads();

        int gwarp = (((int)blockIdx.x - ebA) * blockDim.x + tid) >> 5;
        int lane  = tid & 31;
        int n0 = gwarp * 4;
        if (n0 >= N) return;

        float4 w = reinterpret_cast<const float4*>(sW)[lane];
        float4 v[4];
#pragma unroll
        for (int r = 0; r < 4; r++) {
            int row = n0 + r;
            if (row >= N) row = 0;                  // safe dummy; store skipped below
            v[r] = __ldcs(reinterpret_cast<const float4*>(x + (size_t)row * 128) + lane);
        }
        float acc[4];
#pragma unroll
        for (int r = 0; r < 4; r++)
            acc[r] = v[r].x * w.x + v[r].y * w.y + v[r].z * w.z + v[r].w * w.w;
#pragma unroll
        for (int o = 16; o; o >>= 1) {
#pragma unroll
            for (int r = 0; r < 4; r++)
                acc[r] += __shfl_xor_sync(0xFFFFFFFFu, acc[r], o);
        }
        if (lane < 4) {
            int node = n0 + lane;
            if (node < N) {
                float a_s = att_src[0];
                float a_d = att_dst[0];
                float h  = acc[lane];
                float as = h * a_s;
                float ad = h * a_d;
                float p  = expf(lrelu(as + ad));    // self-loop term
                // single 4B per-node value; which quantity depends on the case
                float av = (a_s != 0.0f) ? as : ((a_d != 0.0f) ? ad : h);
                g_a[node]     = av;
                g_acc[node]   = make_float2(h * p, p);
                g_eself[node] = p;
            }
        }
    }
}

// K2: 4 edges/thread. BOTH random gathers hit the 400KB g_a array (L1-friendly);
// one vec-atomic per edge into g_acc.
__global__ void k_edge1(const void* __restrict__ ei,
                        const float* __restrict__ att_src, const float* __restrict__ att_dst,
                        int E, int N) {
    int is64 = probe_is64((const int*)ei, E);
    float e_s, e_d, h_c;
    att_coeffs(att_src[0], att_dst[0], e_s, e_d, h_c);

    int base = (blockIdx.x * blockDim.x + threadIdx.x) * 4;
    if (base >= E) return;
    if (base + 4 <= E) {
        int s[4], d[4];
        load_edges4(ei, E, N, base, is64, s, d);
        float av_s[4], av_d[4];
#pragma unroll
        for (int k = 0; k < 4; k++) av_s[k] = __ldg(&g_a[s[k]]);
#pragma unroll
        for (int k = 0; k < 4; k++) av_d[k] = __ldg(&g_a[d[k]]);
        float p[4];
#pragma unroll
        for (int k = 0; k < 4; k++)
            p[k] = expf(lrelu(av_s[k] * e_s + av_d[k] * e_d));
        *reinterpret_cast<float4*>(g_p + base) = make_float4(p[0], p[1], p[2], p[3]);
#pragma unroll
        for (int k = 0; k < 4; k++)
            red_add_v2(&g_acc[d[k]], av_s[k] * h_c * p[k], p[k]);
    } else {
        for (int j = base; j < E; j++) {
            int s, d;
            load_edge1(ei, E, N, j, is64, s, d);
            float avs = g_a[s];
            float p = expf(lrelu(avs * e_s + g_a[d] * e_d));
            g_p[j] = p;
            red_add_v2(&g_acc[d], avs * h_c * p, p);
        }
    }
}

// KB (fused): blocks [0, nb2) finalize scores + self-loop slots; blocks
// [nb2, ...) produce per-edge alpha (gather denom directly).
__global__ void k_fuseB(float* __restrict__ out, const float* __restrict__ bias,
                        int E, int N, long long Ell, long long M, int full, int nb2) {
    int tid = threadIdx.x;
    if ((int)blockIdx.x < nb2) {
        int i = blockIdx.x * blockDim.x + tid;
        if (i >= N) return;
        float2 acc = g_acc[i];
        float inv = 1.0f / (acc.y + 1e-16f);
        out[i] = bias[0] + acc.x * inv;
        if (full) {
            size_t base = (size_t)N;
            float fi = (float)i;
            out[base + Ell + i]         = fi;               // src, self-loop slot
            out[base + M + Ell + i]     = fi;               // dst, self-loop slot
            out[base + 2 * M + Ell + i] = g_eself[i] * inv; // alpha, self-loop slot
        }
    } else {
        // edge-alpha role: read dst back from out's float-dst stream (exact < 2^24)
        int base = (((int)blockIdx.x - nb2) * blockDim.x + tid) * 4;
        if (base >= E) return;
        size_t b = (size_t)N + base;
        if (base + 4 <= E) {
            float4 fd = *reinterpret_cast<const float4*>(out + b + M);
            float4 pv = *reinterpret_cast<const float4*>(g_p + base);
            int d0 = __float2int_rz(fd.x), d1 = __float2int_rz(fd.y);
            int d2 = __float2int_rz(fd.z), d3 = __float2int_rz(fd.w);
            float4 fa = make_float4(pv.x / (__ldg(&g_acc[d0]).y + 1e-16f),
                                    pv.y / (__ldg(&g_acc[d1]).y + 1e-16f),
                                    pv.z / (__ldg(&g_acc[d2]).y + 1e-16f),
                                    pv.w / (__ldg(&g_acc[d3]).y + 1e-16f));
            __stcs(reinterpret_cast<float4*>(out + b + 2 * M), fa);
        } else {
            for (int j = base; j < E; j++) {
                int d = __float2int_rz(out[(size_t)N + M + j]);
                out[(size_t)N + 2 * M + j] = g_p[j] / (g_acc[d].y + 1e-16f);
            }
        }
    }
}

extern "C" void kernel_launch(void* const* d_in, const int* in_sizes, int n_in,
                              void* d_out, int out_size) {
    const float* x       = (const float*)d_in[0];
    const void*  ei      = d_in[1];
    const float* W       = (const float*)d_in[2];
    const float* att_src = (const float*)d_in[3];
    const float* att_dst = (const float*)d_in[4];
    const float* bias    = (const float*)d_in[5];

    int N = in_sizes[0] / 128;
    int E = in_sizes[1] / 2;
    long long M = (long long)E + N;
    int full = ((long long)out_size >= (long long)N + 3 * M) ? 1 : 0;
    float* out = (float*)d_out;

    int eblocks4 = ((E + 3) / 4 + 255) / 256;     // 4 edges/thread kernels
    int nblocks1 = (N + 31) / 32;                 // node role: 8 warps/block, 4 nodes/warp
    int nblocks2 = (N + 255) / 256;               // node finalize: 1 node/thread

    int ebA = full ? eblocks4 : 0;
    k_fuseA<<<ebA + nblocks1, 256>>>(ei, x, W, att_src, att_dst, out, E, N, M, ebA);
    k_edge1<<<eblocks4, 256>>>(ei, att_src, att_dst, E, N);
    int ebB = full ? eblocks4 : 0;
    k_fuseB<<<nblocks2 + ebB, 256>>>(out, bias, E, N, (long long)E, M, full, nblocks2);
}